// round 12
// baseline (speedup 1.0000x reference)
#include <cuda_runtime.h>
#include <cuda_bf16.h>
#include <cstdint>

// ---------------- problem constants ----------------
constexpr int kH = 1024;
constexpr int kS = 2048;
constexpr int kB = 4;
constexpr int kM = kB * kS;          // 8192

// ---------------- scratch (tf32-rounded fp32 operands) ----------------
__device__ __align__(256) float g_X [(size_t)kM * kH];
__device__ __align__(256) float g_W [(size_t)3 * kH * kH];
__device__ __align__(256) float g_Q [(size_t)kM * kH];
__device__ __align__(256) float g_K [(size_t)kM * kH];
__device__ __align__(256) float g_Vt[(size_t)kB * kH * kS];     // [b][h][s]
__device__ __align__(256) float g_Sc[(size_t)kB * kS * kS];     // scores -> attn (in-place)

// ---------------- helpers ----------------
__device__ __forceinline__ uint32_t smem_u32(const void* p) {
    uint32_t a;
    asm("{ .reg .u64 t; cvta.to.shared.u64 t, %1; cvt.u32.u64 %0, t; }" : "=r"(a) : "l"(p));
    return a;
}
__device__ __forceinline__ float rna_tf32(float x) {
    uint32_t o;
    asm("cvt.rna.tf32.f32 %0, %1;" : "=r"(o) : "f"(x));
    return __uint_as_float(o);
}

#define CP_ASYNC16(dst, src) \
    asm volatile("cp.async.cg.shared.global [%0], [%1], 16;" :: "r"(dst), "l"(src) : "memory")
#define CP_COMMIT() asm volatile("cp.async.commit_group;" ::: "memory")
#define CP_WAIT1()  asm volatile("cp.async.wait_group 1;" ::: "memory")

__device__ __forceinline__ void mma_tf32(float* c, const uint32_t* a, const uint32_t* b) {
    asm volatile(
        "mma.sync.aligned.m16n8k8.row.col.f32.tf32.tf32.f32 "
        "{%0,%1,%2,%3}, {%4,%5,%6,%7}, {%8,%9}, {%0,%1,%2,%3};"
        : "+f"(c[0]), "+f"(c[1]), "+f"(c[2]), "+f"(c[3])
        : "r"(a[0]), "r"(a[1]), "r"(a[2]), "r"(a[3]), "r"(b[0]), "r"(b[1]));
}

// ---------------- tiling ----------------
// CTA tile 128(M) x 256(N), BK=32. 8 warps in 2(m) x 4(n); warp tile 64x64.
// smem row: 32 data floats + 4 pad = 36 floats = 144 B (conflict-free fragments).
// stage = A(128 rows) + B(256 rows) = 384 * 144 = 55296 B; 3 stages = 162 KB.
constexpr int ROWF  = 36;
constexpr int ROWB  = 144;
constexpr int SM_B  = 128 * ROWB;          // 18432
constexpr int STAGE = 384 * ROWB;          // 55296
constexpr int NSTG  = 3;
constexpr int SMEM_BYTES = NSTG * STAGE;   // 165888

// ---------------------------------------------------------------------------
// mainloop: acc[4][8][4] += A[128,K] x B[256,K]^T (tf32, NT), 256 threads.
// 3-stage cp.async pipeline, one __syncthreads per iteration.
// ---------------------------------------------------------------------------
__device__ __forceinline__ void run_mainloop(
    float acc[4][8][4],
    const float* __restrict__ A, const float* __restrict__ B,
    int lda, int ldb, int niter, char* smem)
{
    const int tid = threadIdx.x, lane = tid & 31, wid = tid >> 5;
    const int wm = wid >> 2, wn = wid & 3;          // 2 x 4 warp grid
    const uint32_t sbase = smem_u32(smem);

    #pragma unroll
    for (int i = 0; i < 4; i++)
        #pragma unroll
        for (int j = 0; j < 8; j++)
            #pragma unroll
            for (int c = 0; c < 4; c++) acc[i][j][c] = 0.0f;

    // cp.async: A 1024 chunks + B 2048 chunks of 16B; 12 chunks/thread.
    auto load_stage = [&](int it, int buf) {
        const uint32_t st = sbase + (uint32_t)buf * STAGE;
        const int k0 = it * 32;
        #pragma unroll
        for (int t = 0; t < 4; t++) {               // A: 128 rows x 8 chunks
            const int ch = tid + t * 256;
            const int r = ch >> 3, c = ch & 7;
            CP_ASYNC16(st + (uint32_t)(r * ROWB + c * 16),
                       A + (size_t)r * lda + k0 + c * 4);
        }
        #pragma unroll
        for (int t = 0; t < 8; t++) {               // B: 256 rows x 8 chunks
            const int ch = tid + t * 256;
            const int r = ch >> 3, c = ch & 7;
            CP_ASYNC16(st + SM_B + (uint32_t)(r * ROWB + c * 16),
                       B + (size_t)r * ldb + k0 + c * 4);
        }
    };

    // fragment byte offsets within a stage
    uint32_t a_base[4], b_base[8];
    #pragma unroll
    for (int i = 0; i < 4; i++)
        a_base[i] = (uint32_t)(((wm * 64 + i * 16 + (lane >> 2)) * ROWF + (lane & 3)) * 4);
    #pragma unroll
    for (int j = 0; j < 8; j++)
        b_base[j] = (uint32_t)(SM_B + ((wn * 64 + j * 8 + (lane >> 2)) * ROWF + (lane & 3)) * 4);

    load_stage(0, 0); CP_COMMIT();
    load_stage(1, 1); CP_COMMIT();

    int buf = 0, nbuf = 2;
    for (int it = 0; it < niter; ++it) {
        CP_WAIT1();              // stage `it` resident
        __syncthreads();         // reads of stage it-1 retired -> nbuf reusable

        if (it + 2 < niter) load_stage(it + 2, nbuf);
        CP_COMMIT();

        const char* st = smem + buf * STAGE;
        #pragma unroll
        for (int ks = 0; ks < 4; ++ks) {
            const uint32_t ko = ks * 32;            // 8 floats per k8 step
            uint32_t a[4][4], b[8][2];
            #pragma unroll
            for (int i = 0; i < 4; i++) {
                const char* p = st + a_base[i] + ko;
                a[i][0] = *(const uint32_t*)(p);
                a[i][1] = *(const uint32_t*)(p + 8 * ROWB);
                a[i][2] = *(const uint32_t*)(p + 16);
                a[i][3] = *(const uint32_t*)(p + 8 * ROWB + 16);
            }
            #pragma unroll
            for (int j = 0; j < 8; j++) {
                const char* p = st + b_base[j] + ko;
                b[j][0] = *(const uint32_t*)(p);
                b[j][1] = *(const uint32_t*)(p + 16);
            }
            #pragma unroll
            for (int i = 0; i < 4; i++)
                #pragma unroll
                for (int j = 0; j < 8; j++)
                    mma_tf32(acc[i][j], a[i], b[j]);
        }

        buf  = (buf  == NSTG - 1) ? 0 : buf + 1;
        nbuf = (nbuf == NSTG - 1) ? 0 : nbuf + 1;
    }
}

// epilogue mapping: m = rowb + wm*64 + i*16 + (lane>>2) (+8 for c2/c3)
//                   n = colb + wn*64 + j*8 + (lane&3)*2 (+1)

// ---------------- kernel 1: QKV projection ----------------
__global__ __launch_bounds__(256, 1)
void qkv_gemm(const float* __restrict__ bq, const float* __restrict__ bk,
              const float* __restrict__ bv)
{
    extern __shared__ char smem[];
    const int z = blockIdx.z;
    const size_t rowb = (size_t)blockIdx.y * 128;
    const size_t colb = (size_t)blockIdx.x * 256;
    float acc[4][8][4];
    run_mainloop(acc, g_X + rowb * kH,
                      g_W + ((size_t)z * kH + colb) * kH,
                 kH, kH, kH / 32, smem);

    const float* bias = (z == 0) ? bq : (z == 1) ? bk : bv;
    const int tid = threadIdx.x, lane = tid & 31, wid = tid >> 5;
    const int wm = wid >> 2, wn = wid & 3;
    const int mloc0 = (int)rowb + wm * 64 + (lane >> 2);
    const int nloc0 = (int)colb + wn * 64 + (lane & 3) * 2;

    #pragma unroll
    for (int i = 0; i < 4; i++)
        #pragma unroll
        for (int j = 0; j < 8; j++) {
            const int n = nloc0 + j * 8;
            const float2 bb = *(const float2*)&bias[n];
            #pragma unroll
            for (int half = 0; half < 2; half++) {
                const int m = mloc0 + i * 16 + half * 8;
                const float v0 = rna_tf32(acc[i][j][half * 2 + 0] + bb.x);
                const float v1 = rna_tf32(acc[i][j][half * 2 + 1] + bb.y);
                if (z == 0) {
                    *(float2*)&g_Q[(size_t)m * kH + n] = make_float2(v0, v1);
                } else if (z == 1) {
                    *(float2*)&g_K[(size_t)m * kH + n] = make_float2(v0, v1);
                } else {
                    const int b = m >> 11, s = m & (kS - 1);
                    const size_t base = ((size_t)b * kH + n) * kS + s;
                    g_Vt[base]      = v0;
                    g_Vt[base + kS] = v1;
                }
            }
        }
}

// ---------------- kernel 2: scores = QK^T / 32 ----------------
__global__ __launch_bounds__(256, 1)
void scores_gemm()
{
    extern __shared__ char smem[];
    const int b = blockIdx.z;
    const size_t rowb = (size_t)b * kS + blockIdx.y * 128;
    const size_t colb = (size_t)b * kS + blockIdx.x * 256;
    float acc[4][8][4];
    run_mainloop(acc, g_Q + rowb * kH, g_K + colb * kH, kH, kH, kH / 32, smem);

    const int tid = threadIdx.x, lane = tid & 31, wid = tid >> 5;
    const int wm = wid >> 2, wn = wid & 3;
    const int mloc0 = blockIdx.y * 128 + wm * 64 + (lane >> 2);
    const int nloc0 = blockIdx.x * 256 + wn * 64 + (lane & 3) * 2;

    #pragma unroll
    for (int i = 0; i < 4; i++)
        #pragma unroll
        for (int j = 0; j < 8; j++) {
            const int n = nloc0 + j * 8;
            #pragma unroll
            for (int half = 0; half < 2; half++) {
                const int m = mloc0 + i * 16 + half * 8;
                float2 v = { acc[i][j][half * 2 + 0] * 0.03125f,
                             acc[i][j][half * 2 + 1] * 0.03125f };
                *(float2*)&g_Sc[((size_t)b * kS + m) * kS + n] = v;
            }
        }
}

// ---------------- kernel 3: softmax in place + tf32 rounding ----------------
__global__ __launch_bounds__(256)
void softmax_kernel()
{
    float* row = g_Sc + (size_t)blockIdx.x * kS;
    const int tid = threadIdx.x;

    float v[8];
    float mx = -3.0e38f;
    #pragma unroll
    for (int r = 0; r < 8; r++) { v[r] = row[tid + r * 256]; mx = fmaxf(mx, v[r]); }

    __shared__ float red[256];
    red[tid] = mx; __syncthreads();
    #pragma unroll
    for (int s2 = 128; s2 > 0; s2 >>= 1) {
        if (tid < s2) red[tid] = fmaxf(red[tid], red[tid + s2]);
        __syncthreads();
    }
    mx = red[0]; __syncthreads();

    float sum = 0.0f;
    #pragma unroll
    for (int r = 0; r < 8; r++) { v[r] = __expf(v[r] - mx); sum += v[r]; }
    red[tid] = sum; __syncthreads();
    #pragma unroll
    for (int s2 = 128; s2 > 0; s2 >>= 1) {
        if (tid < s2) red[tid] += red[tid + s2];
        __syncthreads();
    }
    const float inv = 1.0f / red[0];

    #pragma unroll
    for (int r = 0; r < 8; r++)
        row[tid + r * 256] = rna_tf32(v[r] * inv);
}

// ---------------- kernel 4: out = attn @ V ----------------
__global__ __launch_bounds__(256, 1)
void out_gemm(float* __restrict__ out)
{
    extern __shared__ char smem[];
    const int b = blockIdx.z;
    const size_t rowb = (size_t)b * kS + blockIdx.y * 128;
    const size_t colb = (size_t)b * kH + blockIdx.x * 256;
    float acc[4][8][4];
    run_mainloop(acc, g_Sc + rowb * kS, g_Vt + colb * kS, kS, kS, kS / 32, smem);

    const int tid = threadIdx.x, lane = tid & 31, wid = tid >> 5;
    const int wm = wid >> 2, wn = wid & 3;
    const int mloc0 = blockIdx.y * 128 + wm * 64 + (lane >> 2);
    const int nloc0 = blockIdx.x * 256 + wn * 64 + (lane & 3) * 2;

    #pragma unroll
    for (int i = 0; i < 4; i++)
        #pragma unroll
        for (int j = 0; j < 8; j++) {
            const int n = nloc0 + j * 8;
            #pragma unroll
            for (int half = 0; half < 2; half++) {
                const int m = mloc0 + i * 16 + half * 8;
                float2 v = { acc[i][j][half * 2 + 0], acc[i][j][half * 2 + 1] };
                *(float2*)&out[((size_t)b * kS + m) * kH + n] = v;
            }
        }
}

// ---------------- conversion prepass: fp32 -> tf32-rounded fp32 ----------------
__global__ __launch_bounds__(256)
void convX_kernel(const float* __restrict__ X)
{
    const size_t i = ((size_t)blockIdx.x * 256 + threadIdx.x) * 4;
    float4 x = *(const float4*)&X[i];
    x.x = rna_tf32(x.x); x.y = rna_tf32(x.y);
    x.z = rna_tf32(x.z); x.w = rna_tf32(x.w);
    *(float4*)&g_X[i] = x;
}

__global__ __launch_bounds__(256)
void convW_kernel(const float* __restrict__ Wq, const float* __restrict__ Wk,
                  const float* __restrict__ Wv)
{
    const size_t i = ((size_t)blockIdx.x * 256 + threadIdx.x) * 4;
    const int z = (int)(i >> 20);
    const size_t r = i & ((size_t)kH * kH - 1);
    const float* W = (z == 0) ? Wq : (z == 1) ? Wk : Wv;
    float4 x = *(const float4*)&W[r];
    x.x = rna_tf32(x.x); x.y = rna_tf32(x.y);
    x.z = rna_tf32(x.z); x.w = rna_tf32(x.w);
    *(float4*)&g_W[i] = x;
}

// ---------------- entry point ----------------
extern "C" void kernel_launch(void* const* d_in, const int* in_sizes, int n_in,
                              void* d_out, int out_size)
{
    const float* X  = (const float*)d_in[0];
    const float* Wq = (const float*)d_in[1];
    const float* bq = (const float*)d_in[2];
    const float* Wk = (const float*)d_in[3];
    const float* bk = (const float*)d_in[4];
    const float* Wv = (const float*)d_in[5];
    const float* bv = (const float*)d_in[6];
    float* out = (float*)d_out;

    static bool attr_done = false;
    if (!attr_done) {
        cudaFuncSetAttribute(qkv_gemm,    cudaFuncAttributeMaxDynamicSharedMemorySize, SMEM_BYTES);
        cudaFuncSetAttribute(scores_gemm, cudaFuncAttributeMaxDynamicSharedMemorySize, SMEM_BYTES);
        cudaFuncSetAttribute(out_gemm,    cudaFuncAttributeMaxDynamicSharedMemorySize, SMEM_BYTES);
        attr_done = true;
    }

    convX_kernel<<<(int)((size_t)kM * kH / 4 / 256), 256>>>(X);
    convW_kernel<<<(int)((size_t)3 * kH * kH / 4 / 256), 256>>>(Wq, Wk, Wv);
    qkv_gemm   <<<dim3(kH / 256, kM / 128, 3), 256, SMEM_BYTES>>>(bq, bk, bv);
    scores_gemm<<<dim3(kS / 256, kS / 128, kB), 256, SMEM_BYTES>>>();
    softmax_kernel<<<kM, 256>>>();
    out_gemm   <<<dim3(kH / 256, kS / 128, kB), 256, SMEM_BYTES>>>(out);
}

// round 16
// speedup vs baseline: 1.1623x; 1.1623x over previous
#include <cuda_runtime.h>
#include <cuda_bf16.h>
#include <cstdint>

// ---------------- problem constants ----------------
constexpr int kH = 1024;
constexpr int kS = 2048;
constexpr int kB = 4;
constexpr int kM = kB * kS;          // 8192

// ---------------- scratch (tf32-rounded fp32 operands) ----------------
__device__ __align__(256) float g_X [(size_t)kM * kH];
__device__ __align__(256) float g_W [(size_t)3 * kH * kH];
__device__ __align__(256) float g_Q [(size_t)kM * kH];
__device__ __align__(256) float g_K [(size_t)kM * kH];
__device__ __align__(256) float g_Vt[(size_t)kB * kH * kS];     // [b][h][s]
__device__ __align__(256) float g_Sc[(size_t)kB * kS * kS];     // scores -> attn (in-place)

// ---------------- helpers ----------------
__device__ __forceinline__ uint32_t smem_u32(const void* p) {
    uint32_t a;
    asm("{ .reg .u64 t; cvta.to.shared.u64 t, %1; cvt.u32.u64 %0, t; }" : "=r"(a) : "l"(p));
    return a;
}
__device__ __forceinline__ float rna_tf32(float x) {
    uint32_t o;
    asm("cvt.rna.tf32.f32 %0, %1;" : "=r"(o) : "f"(x));
    return __uint_as_float(o);
}

#define CP_ASYNC16(dst, src) \
    asm volatile("cp.async.cg.shared.global [%0], [%1], 16;" :: "r"(dst), "l"(src) : "memory")
#define CP_COMMIT() asm volatile("cp.async.commit_group;" ::: "memory")
#define CP_WAIT1()  asm volatile("cp.async.wait_group 1;" ::: "memory")

__device__ __forceinline__ void ldsm_x4(uint32_t* r, uint32_t addr) {
    asm volatile("ldmatrix.sync.aligned.m8n8.x4.shared.b16 {%0,%1,%2,%3}, [%4];"
                 : "=r"(r[0]), "=r"(r[1]), "=r"(r[2]), "=r"(r[3]) : "r"(addr));
}

__device__ __forceinline__ void mma_tf32(float* c, const uint32_t* a, const uint32_t* b) {
    asm volatile(
        "mma.sync.aligned.m16n8k8.row.col.f32.tf32.tf32.f32 "
        "{%0,%1,%2,%3}, {%4,%5,%6,%7}, {%8,%9}, {%0,%1,%2,%3};"
        : "+f"(c[0]), "+f"(c[1]), "+f"(c[2]), "+f"(c[3])
        : "r"(a[0]), "r"(a[1]), "r"(a[2]), "r"(a[3]), "r"(b[0]), "r"(b[1]));
}

// ---------------- tiling (R11 config: proven 805us base) ----------------
// CTA 128x128, 8 warps 4(m) x 2(n), warp tile 32x64, BK=32, 3-stage.
// smem row: 32 data floats + 4 pad = 36 floats = 144 B.
constexpr int ROWF  = 36;
constexpr int ROWB  = 144;
constexpr int SM_B  = 128 * ROWB;        // 18432
constexpr int STAGE = 2 * 128 * ROWB;    // 36864
constexpr int NSTG  = 3;
constexpr int SMEM_BYTES = NSTG * STAGE; // 110592 (2 CTAs/SM)

// ---------------------------------------------------------------------------
// mainloop: acc[2][8][4] += A[128,K] x B[128,K]^T (tf32, NT), 256 threads.
// ldmatrix.x4 fragment loads (8x8 b16 tile == 8x4 f32 tile; thread map
// [lane>>2][lane&3] matches the tf32 m16n8k8 fragment exactly).
// ---------------------------------------------------------------------------
__device__ __forceinline__ void run_mainloop(
    float acc[2][8][4],
    const float* __restrict__ A, const float* __restrict__ B,
    int lda, int ldb, int niter, char* smem)
{
    const int tid = threadIdx.x, lane = tid & 31, wid = tid >> 5;
    const int wm = wid >> 1, wn = wid & 1;
    const uint32_t sbase = smem_u32(smem);

    #pragma unroll
    for (int i = 0; i < 2; i++)
        #pragma unroll
        for (int j = 0; j < 8; j++)
            #pragma unroll
            for (int c = 0; c < 4; c++) acc[i][j][c] = 0.0f;

    // cp.async: per operand 1024 16B chunks (128 rows x 8), 4 chunks/thread.
    auto load_stage = [&](int it, int buf) {
        const uint32_t st = sbase + (uint32_t)buf * STAGE;
        const int k0 = it * 32;
        #pragma unroll
        for (int t = 0; t < 4; t++) {
            const int ch = tid + t * 256;
            const int r = ch >> 3, c = ch & 7;
            CP_ASYNC16(st +        (uint32_t)(r * ROWB + c * 16), A + (size_t)r * lda + k0 + c * 4);
            CP_ASYNC16(st + SM_B + (uint32_t)(r * ROWB + c * 16), B + (size_t)r * ldb + k0 + c * 4);
        }
    };

    // ldmatrix per-thread base offsets (within stage, before +ks*32)
    // A, tile i (16x8 f32): matrices {rows0-7,k0-3},{rows8-15,k0-3},{rows0-7,k4-7},{rows8-15,k4-7}
    uint32_t a_off[2];
    {
        const int rowi = (lane & 7) + 8 * ((lane >> 3) & 1);
        const int xb   = (lane >> 4) * 16;
        #pragma unroll
        for (int i = 0; i < 2; i++)
            a_off[i] = (uint32_t)((wm * 32 + i * 16 + rowi) * ROWB + xb);
    }
    // B, j-pair jp (16 n-rows x 8 k): matrices {n0-7,k0-3},{n0-7,k4-7},{n8-15,k0-3},{n8-15,k4-7}
    uint32_t b_off[4];
    {
        const int rowi = (lane & 7) + 8 * (lane >> 4);
        const int xb   = ((lane >> 3) & 1) * 16;
        #pragma unroll
        for (int jp = 0; jp < 4; jp++)
            b_off[jp] = (uint32_t)(SM_B + (wn * 64 + jp * 16 + rowi) * ROWB + xb);
    }

    load_stage(0, 0); CP_COMMIT();
    load_stage(1, 1); CP_COMMIT();

    int buf = 0, nbuf = 2;
    for (int it = 0; it < niter; ++it) {
        CP_WAIT1();
        __syncthreads();

        if (it + 2 < niter) load_stage(it + 2, nbuf);
        CP_COMMIT();

        const uint32_t st = sbase + (uint32_t)buf * STAGE;
        #pragma unroll
        for (int ks = 0; ks < 4; ++ks) {
            const uint32_t ko = ks * 32;
            uint32_t a[2][4], bq[4][4];
            ldsm_x4(a[0],  st + a_off[0] + ko);
            ldsm_x4(a[1],  st + a_off[1] + ko);
            ldsm_x4(bq[0], st + b_off[0] + ko);
            ldsm_x4(bq[1], st + b_off[1] + ko);
            ldsm_x4(bq[2], st + b_off[2] + ko);
            ldsm_x4(bq[3], st + b_off[3] + ko);
            #pragma unroll
            for (int i = 0; i < 2; i++)
                #pragma unroll
                for (int jp = 0; jp < 4; jp++) {
                    mma_tf32(acc[i][2 * jp + 0], a[i], &bq[jp][0]);
                    mma_tf32(acc[i][2 * jp + 1], a[i], &bq[jp][2]);
                }
        }

        buf  = (buf  == NSTG - 1) ? 0 : buf + 1;
        nbuf = (nbuf == NSTG - 1) ? 0 : nbuf + 1;
    }
}

// epilogue mapping: warp 4x2, warp tile 32x64
// m = wm*32 + i*16 + (lane>>2) (+8 for c2/c3); n = wn*64 + j*8 + (lane&3)*2 (+1)

// ---------------- kernel 1: QKV projection ----------------
__global__ __launch_bounds__(256, 2)
void qkv_gemm(const float* __restrict__ bq, const float* __restrict__ bk,
              const float* __restrict__ bv)
{
    extern __shared__ char smem[];
    const int z = blockIdx.z;
    const size_t rowb = (size_t)blockIdx.y * 128;
    const size_t colb = (size_t)blockIdx.x * 128;
    float acc[2][8][4];
    run_mainloop(acc, g_X + rowb * kH,
                      g_W + ((size_t)z * kH + colb) * kH,
                 kH, kH, kH / 32, smem);

    const float* bias = (z == 0) ? bq : (z == 1) ? bk : bv;
    const int tid = threadIdx.x, lane = tid & 31, wid = tid >> 5;
    const int wm = wid >> 1, wn = wid & 1;
    const int mloc0 = (int)rowb + wm * 32 + (lane >> 2);
    const int nloc0 = (int)colb + wn * 64 + (lane & 3) * 2;

    #pragma unroll
    for (int i = 0; i < 2; i++)
        #pragma unroll
        for (int j = 0; j < 8; j++) {
            const int n = nloc0 + j * 8;
            const float2 bb = *(const float2*)&bias[n];
            #pragma unroll
            for (int half = 0; half < 2; half++) {
                const int m = mloc0 + i * 16 + half * 8;
                const float v0 = rna_tf32(acc[i][j][half * 2 + 0] + bb.x);
                const float v1 = rna_tf32(acc[i][j][half * 2 + 1] + bb.y);
                if (z == 0) {
                    *(float2*)&g_Q[(size_t)m * kH + n] = make_float2(v0, v1);
                } else if (z == 1) {
                    *(float2*)&g_K[(size_t)m * kH + n] = make_float2(v0, v1);
                } else {
                    const int b = m >> 11, s = m & (kS - 1);
                    const size_t base = ((size_t)b * kH + n) * kS + s;
                    g_Vt[base]      = v0;
                    g_Vt[base + kS] = v1;
                }
            }
        }
}

// ---------------- kernel 2: scores = QK^T / 32 ----------------
__global__ __launch_bounds__(256, 2)
void scores_gemm()
{
    extern __shared__ char smem[];
    const int b = blockIdx.z;
    const size_t rowb = (size_t)b * kS + blockIdx.y * 128;
    const size_t colb = (size_t)b * kS + blockIdx.x * 128;
    float acc[2][8][4];
    run_mainloop(acc, g_Q + rowb * kH, g_K + colb * kH, kH, kH, kH / 32, smem);

    const int tid = threadIdx.x, lane = tid & 31, wid = tid >> 5;
    const int wm = wid >> 1, wn = wid & 1;
    const int mloc0 = blockIdx.y * 128 + wm * 32 + (lane >> 2);
    const int nloc0 = blockIdx.x * 128 + wn * 64 + (lane & 3) * 2;

    #pragma unroll
    for (int i = 0; i < 2; i++)
        #pragma unroll
        for (int j = 0; j < 8; j++) {
            const int n = nloc0 + j * 8;
            #pragma unroll
            for (int half = 0; half < 2; half++) {
                const int m = mloc0 + i * 16 + half * 8;
                float2 v = { acc[i][j][half * 2 + 0] * 0.03125f,
                             acc[i][j][half * 2 + 1] * 0.03125f };
                *(float2*)&g_Sc[((size_t)b * kS + m) * kS + n] = v;
            }
        }
}

// ---------------- kernel 3: softmax in place + tf32 rounding ----------------
__global__ __launch_bounds__(256)
void softmax_kernel()
{
    float* row = g_Sc + (size_t)blockIdx.x * kS;
    const int tid = threadIdx.x;

    float v[8];
    float mx = -3.0e38f;
    #pragma unroll
    for (int r = 0; r < 8; r++) { v[r] = row[tid + r * 256]; mx = fmaxf(mx, v[r]); }

    __shared__ float red[256];
    red[tid] = mx; __syncthreads();
    #pragma unroll
    for (int s2 = 128; s2 > 0; s2 >>= 1) {
        if (tid < s2) red[tid] = fmaxf(red[tid], red[tid + s2]);
        __syncthreads();
    }
    mx = red[0]; __syncthreads();

    float sum = 0.0f;
    #pragma unroll
    for (int r = 0; r < 8; r++) { v[r] = __expf(v[r] - mx); sum += v[r]; }
    red[tid] = sum; __syncthreads();
    #pragma unroll
    for (int s2 = 128; s2 > 0; s2 >>= 1) {
        if (tid < s2) red[tid] += red[tid + s2];
        __syncthreads();
    }
    const float inv = 1.0f / red[0];

    #pragma unroll
    for (int r = 0; r < 8; r++)
        row[tid + r * 256] = rna_tf32(v[r] * inv);
}

// ---------------- kernel 4: out = attn @ V ----------------
__global__ __launch_bounds__(256, 2)
void out_gemm(float* __restrict__ out)
{
    extern __shared__ char smem[];
    const int b = blockIdx.z;
    const size_t rowb = (size_t)b * kS + blockIdx.y * 128;
    const size_t colb = (size_t)b * kH + blockIdx.x * 128;
    float acc[2][8][4];
    run_mainloop(acc, g_Sc + rowb * kS, g_Vt + colb * kS, kS, kS, kS / 32, smem);

    const int tid = threadIdx.x, lane = tid & 31, wid = tid >> 5;
    const int wm = wid >> 1, wn = wid & 1;
    const int mloc0 = blockIdx.y * 128 + wm * 32 + (lane >> 2);
    const int nloc0 = blockIdx.x * 128 + wn * 64 + (lane & 3) * 2;

    #pragma unroll
    for (int i = 0; i < 2; i++)
        #pragma unroll
        for (int j = 0; j < 8; j++) {
            const int n = nloc0 + j * 8;
            #pragma unroll
            for (int half = 0; half < 2; half++) {
                const int m = mloc0 + i * 16 + half * 8;
                float2 v = { acc[i][j][half * 2 + 0], acc[i][j][half * 2 + 1] };
                *(float2*)&out[((size_t)b * kS + m) * kH + n] = v;
            }
        }
}

// ---------------- conversion prepass: fp32 -> tf32-rounded fp32 ----------------
__global__ __launch_bounds__(256)
void convX_kernel(const float* __restrict__ X)
{
    const size_t i = ((size_t)blockIdx.x * 256 + threadIdx.x) * 4;
    float4 x = *(const float4*)&X[i];
    x.x = rna_tf32(x.x); x.y = rna_tf32(x.y);
    x.z = rna_tf32(x.z); x.w = rna_tf32(x.w);
    *(float4*)&g_X[i] = x;
}

__global__ __launch_bounds__(256)
void convW_kernel(const float* __restrict__ Wq, const float* __restrict__ Wk,
                  const float* __restrict__ Wv)
{
    const size_t i = ((size_t)blockIdx.x * 256 + threadIdx.x) * 4;
    const int z = (int)(i >> 20);
    const size_t r = i & ((size_t)kH * kH - 1);
    const float* W = (z == 0) ? Wq : (z == 1) ? Wk : Wv;
    float4 x = *(const float4*)&W[r];
    x.x = rna_tf32(x.x); x.y = rna_tf32(x.y);
    x.z = rna_tf32(x.z); x.w = rna_tf32(x.w);
    *(float4*)&g_W[i] = x;
}

// ---------------- entry point ----------------
extern "C" void kernel_launch(void* const* d_in, const int* in_sizes, int n_in,
                              void* d_out, int out_size)
{
    const float* X  = (const float*)d_in[0];
    const float* Wq = (const float*)d_in[1];
    const float* bq = (const float*)d_in[2];
    const float* Wk = (const float*)d_in[3];
    const float* bk = (const float*)d_in[4];
    const float* Wv = (const float*)d_in[5];
    const float* bv = (const float*)d_in[6];
    float* out = (float*)d_out;

    static bool attr_done = false;
    if (!attr_done) {
        cudaFuncSetAttribute(qkv_gemm,    cudaFuncAttributeMaxDynamicSharedMemorySize, SMEM_BYTES);
        cudaFuncSetAttribute(scores_gemm, cudaFuncAttributeMaxDynamicSharedMemorySize, SMEM_BYTES);
        cudaFuncSetAttribute(out_gemm,    cudaFuncAttributeMaxDynamicSharedMemorySize, SMEM_BYTES);
        attr_done = true;
    }

    convX_kernel<<<(int)((size_t)kM * kH / 4 / 256), 256>>>(X);
    convW_kernel<<<(int)((size_t)3 * kH * kH / 4 / 256), 256>>>(Wq, Wk, Wv);
    qkv_gemm   <<<dim3(kH / 128, kM / 128, 3), 256, SMEM_BYTES>>>(bq, bk, bv);
    scores_gemm<<<dim3(kS / 128, kS / 128, kB), 256, SMEM_BYTES>>>();
    softmax_kernel<<<kM, 256>>>();
    out_gemm   <<<dim3(kH / 128, kS / 128, kB), 256, SMEM_BYTES>>>(out);
}